// round 1
// baseline (speedup 1.0000x reference)
#include <cuda_runtime.h>
#include <math.h>

#define HID   32
#define LEN   32768
#define HOP   256
#define KL    128
#define OUTC  64
#define BATCH 16

#define HS_STRIDE 272   // 264 needed + pad (conflict/vec friendly)
#define XS_STRIDE 265   // 264 needed + 1 pad (stride 265 mod 32 = 9, conflict-free stores)

// Scratch: kernel tensor transposed to [b][l][i][o][k] for coalesced per-CTA loads.
__device__ float g_kt[(size_t)BATCH * KL * HID * OUTC * 3];  // 12.58 M floats = 50.3 MB

// ---------------------------------------------------------------------------
// Pass 1: transpose kernel[b, i, o, k, l] (l fastest) -> g_kt[b, l, m] where
// m = (i*64+o)*3+k. Per b it's a 6144 x 128 matrix transpose. 32x32 smem tiles.
// ---------------------------------------------------------------------------
__global__ void transpose_kernel_tensor(const float* __restrict__ kin) {
    __shared__ float tile[32][33];
    int b  = blockIdx.z;
    int m0 = blockIdx.x * 32;   // 192 tiles over m=6144
    int l0 = blockIdx.y * 32;   // 4 tiles over l=128
    int tx = threadIdx.x, ty = threadIdx.y;
    const float* src = kin + (size_t)b * 6144 * 128;
    float*       dst = g_kt + (size_t)b * 128 * 6144;
#pragma unroll
    for (int r = 0; r < 4; r++) {
        int m = m0 + ty + r * 8;
        tile[ty + r * 8][tx] = src[(size_t)m * 128 + l0 + tx];   // coalesced along l
    }
    __syncthreads();
#pragma unroll
    for (int r = 0; r < 4; r++) {
        int l = l0 + ty + r * 8;
        dst[(size_t)l * 6144 + m0 + tx] = tile[tx][ty + r * 8];  // coalesced along m
    }
}

// ---------------------------------------------------------------------------
// Pass 2: fused leaky -> dilated conv -> leaky -> LVC -> gate -> +residual.
// One CTA per (l chunk, batch). 256 threads, ~104 KB dynamic smem, 2 CTA/SM.
// ---------------------------------------------------------------------------
__global__ __launch_bounds__(256, 2)
void lvc_block_kernel(const float* __restrict__ hidden,
                      const float* __restrict__ bias,
                      const float* __restrict__ conv_w,
                      const float* __restrict__ conv_b,
                      float* __restrict__ out) {
    extern __shared__ float sm[];
    float* ks    = sm;                     // 6144 : ks[i*192 + o*3 + k]
    float* wt    = ks + 6144;              // 3072 : wt[(ci*3+k)*32 + c]  (c contiguous)
    float* biasS = wt + 3072;              // 64
    float* cbS   = biasS + 64;             // 32
    float* hs    = cbS + 32;               // 32*272 : leaky(hidden), hs[c][u] <-> g = cs-7+u
    float* xs    = hs + 32 * HS_STRIDE;    // 32*265 : conv output, xs[c][u2] <-> chunk pos u2-4

    const int tid = threadIdx.x;
    const int l = blockIdx.x, b = blockIdx.y;
    const int cs = l * HOP;

    // --- Load LVC filter (coalesced float4 copy of 24 KB) ---
    {
        const float4* ktsrc = (const float4*)(g_kt + ((size_t)b * KL + l) * 6144);
        float4* ksd = (float4*)ks;
        for (int idx = tid; idx < 1536; idx += 256) ksd[idx] = ktsrc[idx];
    }
    // --- Conv weights, transposed so lane index (=out channel) is contiguous ---
    for (int idx = tid; idx < 3072; idx += 256) {
        int c = idx / 96, r = idx % 96;          // r = ci*3 + k
        wt[r * 32 + c] = conv_w[idx];
    }
    if (tid < 64) biasS[tid] = bias[((size_t)b * 64 + tid) * 128 + l];
    if (tid < 32) cbS[tid]   = conv_b[tid];

    // --- Load leaky(hidden) halo tile [32][272], zero outside [0, LEN) ---
    const float* hidB = hidden + (size_t)b * HID * LEN;
    for (int idx = tid; idx < 32 * HS_STRIDE; idx += 256) {
        int c = idx / HS_STRIDE, u = idx % HS_STRIDE;
        int g = cs - 7 + u;
        float v = (g >= 0 && g < LEN) ? hidB[(size_t)c * LEN + g] : 0.f;
        hs[idx] = (v >= 0.f) ? v : 0.2f * v;
    }
    __syncthreads();

    // --- Dilated conv: thread = (out channel c = lane, t-block of 33) ---
    // Output chunk position t_c = tb*33 - 4 + t  (covers [-4, 259] superset of [-1,256]).
    // hs loads are warp-broadcast; wt loads are lane-contiguous: conflict-free.
    {
        const int c  = tid & 31;
        const int tb = tid >> 5;
        float acc[33];
#pragma unroll
        for (int t = 0; t < 33; t++) acc[t] = 0.f;
        for (int ci = 0; ci < 32; ci++) {
            float w0 = wt[(ci * 3 + 0) * 32 + c];
            float w1 = wt[(ci * 3 + 1) * 32 + c];
            float w2 = wt[(ci * 3 + 2) * 32 + c];
            const float* hrow = hs + ci * HS_STRIDE + tb * 33;
            float hv[39];
#pragma unroll
            for (int j = 0; j < 39; j++) hv[j] = hrow[j];
#pragma unroll
            for (int t = 0; t < 33; t++)
                acc[t] += w0 * hv[t] + w1 * hv[t + 3] + w2 * hv[t + 6];
        }
        float cb = cbS[c];
        float* xrow = xs + c * XS_STRIDE + tb * 33;
        int pbase = cs + tb * 33 - 4;
#pragma unroll
        for (int t = 0; t < 33; t++) {
            int p = pbase + t;                // global position of this conv output
            float v = acc[t] + cb;
            v = (v >= 0.f) ? v : 0.2f * v;
            // Reference zero-pads the CONV OUTPUT for the LVC window:
            xrow[t] = (p >= 0 && p < LEN) ? v : 0.f;
        }
    }
    __syncthreads();

    // --- LVC: thread = (ob = tid&7, sb = tid>>3); o = ob + 8*oi, s = 8*sb + j ---
    // 64 accumulators/thread; ks lane addresses stride 3 floats -> conflict-free;
    // xs reads are 4-address broadcast.
    const int ob = tid & 7;
    const int sb = tid >> 3;
    const int s0 = sb * 8;
    float a[8][8];
#pragma unroll
    for (int oi = 0; oi < 8; oi++)
#pragma unroll
        for (int j = 0; j < 8; j++) a[oi][j] = 0.f;

    for (int i = 0; i < 32; i++) {
        // x at chunk pos (s + k - 1) lives at xs index s + k + 3
        const float* xr = xs + i * XS_STRIDE + s0 + 3;
        float xv[10];
#pragma unroll
        for (int j = 0; j < 10; j++) xv[j] = xr[j];
        const float* kr = ks + i * 192;
#pragma unroll
        for (int oi = 0; oi < 8; oi++) {
            int o = ob + 8 * oi;
            float k0 = kr[o * 3 + 0];
            float k1 = kr[o * 3 + 1];
            float k2 = kr[o * 3 + 2];
#pragma unroll
            for (int j = 0; j < 8; j++)
                a[oi][j] += k0 * xv[j] + k1 * xv[j + 1] + k2 * xv[j + 2];
        }
    }

    // --- Gate + residual. Pairs: (o = ob+8*oi, o+32) = (a[oi], a[oi+4]) ---
    const float* hidC = hidB + cs;
    float* outC = out + (size_t)b * HID * LEN + cs;
#pragma unroll
    for (int oi = 0; oi < 4; oi++) {
        int o = ob + 8 * oi;                 // output channel 0..31
        float bg = biasS[o], bh = biasS[o + 32];
        float4 r0 = *(const float4*)(hidC + (size_t)o * LEN + s0);
        float4 r1 = *(const float4*)(hidC + (size_t)o * LEN + s0 + 4);
        float res[8] = {r0.x, r0.y, r0.z, r0.w, r1.x, r1.y, r1.z, r1.w};
        float yo[8];
#pragma unroll
        for (int j = 0; j < 8; j++) {
            float gv = a[oi][j] + bg;
            float hv = a[oi + 4][j] + bh;
            float sig = 1.f / (1.f + __expf(-gv));
            yo[j] = res[j] + sig * tanhf(hv);
        }
        *(float4*)(outC + (size_t)o * LEN + s0)     = make_float4(yo[0], yo[1], yo[2], yo[3]);
        *(float4*)(outC + (size_t)o * LEN + s0 + 4) = make_float4(yo[4], yo[5], yo[6], yo[7]);
    }
}

// ---------------------------------------------------------------------------
extern "C" void kernel_launch(void* const* d_in, const int* in_sizes, int n_in,
                              void* d_out, int out_size) {
    const float* hidden = (const float*)d_in[0];
    const float* kern   = (const float*)d_in[1];
    const float* bias   = (const float*)d_in[2];
    const float* conv_w = (const float*)d_in[3];
    const float* conv_b = (const float*)d_in[4];
    // d_in[5] = hop_size (constant 256, baked in)
    float* out = (float*)d_out;

    transpose_kernel_tensor<<<dim3(192, 4, 16), dim3(32, 8)>>>(kern);

    int smem_bytes = (6144 + 3072 + 64 + 32 + 32 * HS_STRIDE + 32 * XS_STRIDE) * 4;  // 105,984 B
    cudaFuncSetAttribute(lvc_block_kernel,
                         cudaFuncAttributeMaxDynamicSharedMemorySize, smem_bytes);
    lvc_block_kernel<<<dim3(KL, BATCH), 256, smem_bytes>>>(hidden, bias, conv_w, conv_b, out);
}

// round 2
// speedup vs baseline: 1.0558x; 1.0558x over previous
#include <cuda_runtime.h>
#include <math.h>

#define HID   32
#define LEN   32768
#define HOP   256
#define KL    128
#define OUTC  64
#define BATCH 16

#define HSS 268   // hs row stride (264 needed, mod 4 == 0 for float4 rows)
#define XSS 260   // xs row stride (258 needed, mod 4 == 0)

// Scratch: kernel tensor transposed+padded to [b][l][i][o][4] for coalesced loads
// and single-LDS.128 per (i,o) in the main kernel.
__device__ float g_kt[(size_t)BATCH * KL * HID * OUTC * 4];  // 67 MB

__device__ __forceinline__ float fast_tanh(float x) {
    float r; asm("tanh.approx.f32 %0, %1;" : "=f"(r) : "f"(x)); return r;
}
__device__ __forceinline__ float fast_ex2(float x) {
    float r; asm("ex2.approx.f32 %0, %1;" : "=f"(r) : "f"(x)); return r;
}
__device__ __forceinline__ float fast_rcp(float x) {
    float r; asm("rcp.approx.f32 %0, %1;" : "=f"(r) : "f"(x)); return r;
}

// ---------------------------------------------------------------------------
// Pass 1: kernel[b, i, o, k, l] (l fastest) -> g_kt[b][l][ i*256 + o*4 + k ]
// ---------------------------------------------------------------------------
__global__ void transpose_kernel_tensor(const float* __restrict__ kin) {
    __shared__ float tile[32][33];
    int b  = blockIdx.z;
    int m0 = blockIdx.x * 32;   // 192 tiles over m = 6144 (i*192 + o*3 + k)
    int l0 = blockIdx.y * 32;   // 4 tiles over l = 128
    int tx = threadIdx.x, ty = threadIdx.y;
    const float* src = kin + (size_t)b * 6144 * 128;
    float*       dst = g_kt + (size_t)b * 128 * 8192;
#pragma unroll
    for (int r = 0; r < 4; r++) {
        int m = m0 + ty + r * 8;
        tile[ty + r * 8][tx] = src[(size_t)m * 128 + l0 + tx];   // coalesced along l
    }
    __syncthreads();
#pragma unroll
    for (int r = 0; r < 4; r++) {
        int l = l0 + ty + r * 8;
        int m = m0 + tx;
        int mp = (m / 3) * 4 + (m % 3);        // padded index
        dst[(size_t)l * 8192 + mp] = tile[tx][ty + r * 8];
    }
}

// ---------------------------------------------------------------------------
// Pass 2: fused leaky -> dilated conv -> leaky -> LVC -> gate -> +residual.
// One CTA per (l chunk, batch). 256 threads, ~110 KB smem, 2 CTA/SM.
// ---------------------------------------------------------------------------
__global__ __launch_bounds__(256, 2)
void lvc_block_kernel(const float* __restrict__ hidden,
                      const float* __restrict__ bias,
                      const float* __restrict__ conv_w,
                      const float* __restrict__ conv_b,
                      float* __restrict__ out) {
    extern __shared__ float sm[];
    float* ks    = sm;                     // 8192 : ks[i*256 + o*4 + k] (k=3 pad)
    float* wt    = ks + 8192;              // 3072 : wt[(ci*3+k)*32 + c]
    float* biasS = wt + 3072;              // 64
    float* cbS   = biasS + 64;             // 32
    float* hs    = cbS + 32;               // 32*268 : leaky(hidden), hs[c][u] <-> g = cs-4+u
    float* xs    = hs + 32 * HSS;          // 32*260 : conv out, xs[c][u] <-> chunk pos u-1

    const int tid = threadIdx.x;
    const int l = blockIdx.x, b = blockIdx.y;
    const int cs = l * HOP;

    // --- LVC filter: coalesced float4 copy of 32 KB ---
    {
        const float4* ktsrc = (const float4*)(g_kt + ((size_t)b * KL + l) * 8192);
        float4* ksd = (float4*)ks;
        for (int idx = tid; idx < 2048; idx += 256) ksd[idx] = ktsrc[idx];
    }
    // --- Conv weights transposed so lane (= out channel) is contiguous ---
    for (int idx = tid; idx < 3072; idx += 256) {
        int c = idx / 96, r = idx % 96;          // r = ci*3 + k
        wt[r * 32 + c] = conv_w[idx];
    }
    if (tid < 64) biasS[tid] = bias[((size_t)b * 64 + tid) * 128 + l];
    if (tid < 32) cbS[tid]   = conv_b[tid];

    // --- Load leaky(hidden) halo tile [32][268], zero outside [0, LEN) ---
    const float* hidB = hidden + (size_t)b * HID * LEN;
    for (int idx = tid; idx < 32 * HSS; idx += 256) {
        int c = idx / HSS, u = idx % HSS;
        int g = cs - 4 + u;
        float v = (g >= 0 && g < LEN) ? hidB[(size_t)c * LEN + g] : 0.f;
        hs[idx] = (v >= 0.f) ? v : 0.2f * v;
    }
    __syncthreads();

    // --- Dilated conv: thread = (c = tid&31, tb = tid>>5), 32 aligned outputs ---
    // Output chunk pos p = tb*32 + t; h tap at pos p+3(k-1) lives at hs index p+1+3k.
    {
        const int c  = tid & 31;
        const int tb = tid >> 5;               // constant per warp -> hs reads broadcast
        float acc[32];
#pragma unroll
        for (int t = 0; t < 32; t++) acc[t] = 0.f;
        for (int ci = 0; ci < 32; ci++) {
            float w0 = wt[(ci * 3 + 0) * 32 + c];
            float w1 = wt[(ci * 3 + 1) * 32 + c];
            float w2 = wt[(ci * 3 + 2) * 32 + c];
            const float* hrow = hs + ci * HSS + tb * 32;   // 16B aligned
            {
                float h0[24];
#pragma unroll
                for (int jj = 0; jj < 6; jj++) ((float4*)h0)[jj] = ((const float4*)hrow)[jj];
#pragma unroll
                for (int t = 0; t < 16; t++)
                    acc[t] += w0 * h0[t + 1] + w1 * h0[t + 4] + w2 * h0[t + 7];
            }
            {
                float h1[24];
#pragma unroll
                for (int jj = 0; jj < 6; jj++) ((float4*)h1)[jj] = ((const float4*)(hrow + 16))[jj];
#pragma unroll
                for (int t = 0; t < 16; t++)
                    acc[16 + t] += w0 * h1[t + 1] + w1 * h1[t + 4] + w2 * h1[t + 7];
            }
        }
        float cb = cbS[c];
        float* xrow = xs + c * XSS + tb * 32 + 1;   // xs index u = p + 1
#pragma unroll
        for (int t = 0; t < 32; t++) {
            float v = acc[t] + cb;
            xrow[t] = (v >= 0.f) ? v : 0.2f * v;    // p in [0,256) always inside [0,LEN)
        }
        // Boundary LVC-window positions p = -1 and p = 256 (zero outside [0,LEN))
        if (tid < 64) {
            int c2 = tid & 31;
            int p  = (tid < 32) ? -1 : 256;
            int u0 = p + 1;                         // 0 or 257; taps at u0 + 3k
            float accv = 0.f;
            for (int ci = 0; ci < 32; ci++) {
                const float* hr = hs + ci * HSS + u0;
                accv += wt[(ci * 3 + 0) * 32 + c2] * hr[0]
                      + wt[(ci * 3 + 1) * 32 + c2] * hr[3]
                      + wt[(ci * 3 + 2) * 32 + c2] * hr[6];
            }
            float v = accv + cbS[c2];
            v = (v >= 0.f) ? v : 0.2f * v;
            int gp = cs + p;
            xs[c2 * XSS + u0] = (gp >= 0 && gp < LEN) ? v : 0.f;
        }
    }
    __syncthreads();

    // --- LVC: thread = (ob = tid&7, sb = tid>>3); o = ob + 8*oi, s = 8*sb + j ---
    const int ob = tid & 7;
    const int sb = tid >> 3;
    const int s0 = sb * 8;
    float a[8][8];
#pragma unroll
    for (int oi = 0; oi < 8; oi++)
#pragma unroll
        for (int j = 0; j < 8; j++) a[oi][j] = 0.f;

    const float4* ks4 = (const float4*)ks;
    for (int i = 0; i < 32; i++) {
        // x at chunk pos s+k-1 lives at xs index s+k -> xv[t] = xs[i][s0+t], t = j+k
        float xv[12];
        const float4* xr = (const float4*)(xs + i * XSS + s0);
#pragma unroll
        for (int jj = 0; jj < 3; jj++) ((float4*)xv)[jj] = xr[jj];
#pragma unroll
        for (int oi = 0; oi < 8; oi++) {
            float4 kv = ks4[i * 64 + ob + 8 * oi];   // one LDS.128, conflict-free
#pragma unroll
            for (int j = 0; j < 8; j++)
                a[oi][j] += kv.x * xv[j] + kv.y * xv[j + 1] + kv.z * xv[j + 2];
        }
    }

    // --- Gate + residual. Pairs (o, o+32) = (a[oi], a[oi+4]) ---
    const float* hidC = hidB + cs;
    float* outC = out + (size_t)b * HID * LEN + cs;
    const float LOG2E = 1.4426950408889634f;
#pragma unroll
    for (int oi = 0; oi < 4; oi++) {
        int o = ob + 8 * oi;                 // output channel 0..31
        float bg = biasS[o], bh = biasS[o + 32];
        float4 r0 = *(const float4*)(hidC + (size_t)o * LEN + s0);
        float4 r1 = *(const float4*)(hidC + (size_t)o * LEN + s0 + 4);
        float res[8] = {r0.x, r0.y, r0.z, r0.w, r1.x, r1.y, r1.z, r1.w};
        float yo[8];
#pragma unroll
        for (int j = 0; j < 8; j++) {
            float gv = a[oi][j] + bg;
            float hv = a[oi + 4][j] + bh;
            float sig = fast_rcp(1.f + fast_ex2(-LOG2E * gv));
            yo[j] = res[j] + sig * fast_tanh(hv);
        }
        *(float4*)(outC + (size_t)o * LEN + s0)     = make_float4(yo[0], yo[1], yo[2], yo[3]);
        *(float4*)(outC + (size_t)o * LEN + s0 + 4) = make_float4(yo[4], yo[5], yo[6], yo[7]);
    }
}

// ---------------------------------------------------------------------------
extern "C" void kernel_launch(void* const* d_in, const int* in_sizes, int n_in,
                              void* d_out, int out_size) {
    const float* hidden = (const float*)d_in[0];
    const float* kern   = (const float*)d_in[1];
    const float* bias   = (const float*)d_in[2];
    const float* conv_w = (const float*)d_in[3];
    const float* conv_b = (const float*)d_in[4];
    float* out = (float*)d_out;

    transpose_kernel_tensor<<<dim3(192, 4, 16), dim3(32, 8)>>>(kern);

    int smem_bytes = (8192 + 3072 + 64 + 32 + 32 * HSS + 32 * XSS) * 4;  // 113,024 B
    cudaFuncSetAttribute(lvc_block_kernel,
                         cudaFuncAttributeMaxDynamicSharedMemorySize, smem_bytes);
    lvc_block_kernel<<<dim3(KL, BATCH), 256, smem_bytes>>>(hidden, bias, conv_w, conv_b, out);
}